// round 17
// baseline (speedup 1.0000x reference)
#include <cuda_runtime.h>
#include <cuda_fp16.h>

// ---------------------------------------------------------------------------
// QuantumAttention, restructured:
//   out = attn @ (x @ (Wv@Wo) + bv@Wo) + bo,  attn = softmax((q_q.k_q)^2)
//   q_q = normalize(x @ (Wq@We) + (bq@We+be)), k_q likewise.
// R17: fixes a latent cp.async tail race present since R6 — the last K-chunk's
// CP_WAIT(1) was a no-op when only one group remained pending. Fix: ALWAYS
// commit a (possibly empty) group each iteration so the tail wait drains the
// final load. Otherwise identical to R16 (64x128 GEMM tiles, 3 CTAs/SM).
// Expected rel_err: exactly 4.042953e-4.
// ---------------------------------------------------------------------------

#define B_ 4
#define S_ 2048
#define H_ 1024
#define QD_ 16
#define ROWS_ (B_ * S_)          // 8192

typedef unsigned int u32;

// ------------------------------- scratch ----------------------------------
__device__ float g_WqeT[QD_ * H_];
__device__ float g_WkeT[QD_ * H_];
__device__ float g_bqe[QD_];
__device__ float g_bke[QD_];
__device__ float g_qq[ROWS_ * QD_];
__device__ float g_kq[ROWS_ * QD_];
__device__ float g_b2[H_];

__device__ half g_xh[ROWS_ * H_];
__device__ half g_Wvh[H_ * H_];
__device__ half g_Wvl[H_ * H_];
__device__ half g_Woh[H_ * H_];
__device__ half g_Wol[H_ * H_];
__device__ half g_W2h[H_ * H_];
__device__ half g_v2h[ROWS_ * H_];
__device__ half g_attnh[(long long)B_ * S_ * S_];

// ----------------------------- PTX helpers --------------------------------
__device__ __forceinline__ u32 smem_u32(const void* p) {
    u32 a;
    asm("{ .reg .u64 t; cvta.to.shared.u64 t, %1; cvt.u32.u64 %0, t; }"
        : "=r"(a) : "l"(p));
    return a;
}
__device__ __forceinline__ void cpa16(u32 d, const void* g) {
    asm volatile("cp.async.cg.shared.global [%0], [%1], 16;" :: "r"(d), "l"(g));
}
#define CP_COMMIT() asm volatile("cp.async.commit_group;" ::: "memory")
#define CP_WAIT(n)  asm volatile("cp.async.wait_group %0;" :: "n"(n) : "memory")

__device__ __forceinline__ void ldsm4(u32* r, u32 a) {
    asm volatile("ldmatrix.sync.aligned.m8n8.x4.shared.b16 {%0,%1,%2,%3}, [%4];"
        : "=r"(r[0]), "=r"(r[1]), "=r"(r[2]), "=r"(r[3]) : "r"(a));
}
__device__ __forceinline__ void ldsm4t(u32* r, u32 a) {
    asm volatile("ldmatrix.sync.aligned.m8n8.x4.trans.shared.b16 {%0,%1,%2,%3}, [%4];"
        : "=r"(r[0]), "=r"(r[1]), "=r"(r[2]), "=r"(r[3]) : "r"(a));
}
__device__ __forceinline__ void mma16816(float* d, const u32* a, const u32* b) {
    asm volatile("mma.sync.aligned.m16n8k16.row.col.f32.f16.f16.f32 "
        "{%0,%1,%2,%3}, {%4,%5,%6,%7}, {%8,%9}, {%0,%1,%2,%3};"
        : "+f"(d[0]), "+f"(d[1]), "+f"(d[2]), "+f"(d[3])
        : "r"(a[0]), "r"(a[1]), "r"(a[2]), "r"(a[3]), "r"(b[0]), "r"(b[1]));
}

// exp(s), s in [0,1]: degree-6 Taylor around 0.5 (FMA pipe; rel err ~1.3e-6)
__device__ __forceinline__ float exp01(float s) {
    float u = s - 0.5f;
    float p = 1.f / 720.f;
    p = fmaf(p, u, 1.f / 120.f);
    p = fmaf(p, u, 1.f / 24.f);
    p = fmaf(p, u, 1.f / 6.f);
    p = fmaf(p, u, 0.5f);
    p = fmaf(p, u, 1.f);
    p = fmaf(p, u, 1.f);
    return p * 1.6487212707f;
}

// ---------------------------- role bodies ----------------------------------

__device__ __forceinline__ void precompute_body(int bid,
    const float* __restrict__ Wq, const float* __restrict__ Wk,
    const float* __restrict__ We, const float* __restrict__ bq,
    const float* __restrict__ bk, const float* __restrict__ be)
{
    extern __shared__ char dsm[];
    float* Wes = (float*)dsm;               // [1024][17]
    int tid = threadIdx.x;
    for (int idx = tid; idx < H_ * QD_; idx += 256)
        Wes[(idx >> 4) * 17 + (idx & 15)] = We[idx];
    __syncthreads();

    int wg = bid * 8 + (tid >> 5);
    if (wg >= 2 * (H_ + 1)) return;
    int m = wg / (H_ + 1);
    int i = wg % (H_ + 1);
    int lane = tid & 31;
    const float* W  = m ? Wk : Wq;
    const float* bb = m ? bk : bq;

    float p[QD_];
    #pragma unroll
    for (int o = 0; o < QD_; o++) p[o] = 0.f;

    for (int kk = 0; kk < H_ / 32; kk++) {
        int k = kk * 32 + lane;
        float w = (i < H_) ? W[(long long)i * H_ + k] : bb[k];
        const float* wr = &Wes[k * 17];
        #pragma unroll
        for (int o = 0; o < QD_; o++) p[o] = fmaf(w, wr[o], p[o]);
    }
    #pragma unroll
    for (int off = 16; off; off >>= 1)
        #pragma unroll
        for (int o = 0; o < QD_; o++)
            p[o] += __shfl_xor_sync(0xffffffffu, p[o], off);

    if (lane == 0) {
        if (i < H_) {
            float* dst = m ? g_WkeT : g_WqeT;
            #pragma unroll
            for (int o = 0; o < QD_; o++) dst[o * H_ + i] = p[o];
        } else {
            float* dst = m ? g_bke : g_bqe;
            #pragma unroll
            for (int o = 0; o < QD_; o++) dst[o] = p[o] + be[o];
        }
    }
}

__device__ __forceinline__ void b2_body(int bid,
    const float* __restrict__ bv, const float* __restrict__ Wo)
{
    __shared__ float red[8][33];
    int t = threadIdx.x;
    int n = bid * 32 + (t & 31);
    int ks = t >> 5;
    float s = 0.f;
    #pragma unroll 4
    for (int k = ks * 128; k < ks * 128 + 128; k++)
        s = fmaf(bv[k], Wo[(long long)k * H_ + n], s);
    red[ks][t & 31] = s;
    __syncthreads();
    if (t < 32) {
        float tot = 0.f;
        #pragma unroll
        for (int i = 0; i < 8; i++) tot += red[i][t];
        g_b2[bid * 32 + t] = tot;
    }
}

// fp32 -> fp16 hi+lo split of Wv / Wo
__device__ __forceinline__ void split_body(int sidx,
    const float* __restrict__ Wv, const float* __restrict__ Wo)
{
    bool second = sidx >= 1024;
    const float* src = second ? Wo : Wv;
    half* h = second ? g_Woh : g_Wvh;
    half* l = second ? g_Wol : g_Wvl;
    int i = (sidx & 1023) * 256 + threadIdx.x;
    float4 v = ((const float4*)src)[i];
    half a0 = __float2half_rn(v.x), a1 = __float2half_rn(v.y);
    half a2 = __float2half_rn(v.z), a3 = __float2half_rn(v.w);
    half2* hp = (half2*)h;
    half2* lp = (half2*)l;
    hp[2*i]   = __halves2half2(a0, a1);
    hp[2*i+1] = __halves2half2(a2, a3);
    lp[2*i]   = __floats2half2_rn(v.x - __half2float(a0), v.y - __half2float(a1));
    lp[2*i+1] = __floats2half2_rn(v.z - __half2float(a2), v.w - __half2float(a3));
}

// embed (q-or-k half): 64 rows/block, 16 dims; q-blocks also emit xh (fp16).
#define ERB 64
__device__ __forceinline__ void embed_body16(int bid, const float* __restrict__ x,
                                             bool isq)
{
    extern __shared__ char dsm[];
    float* sm = (float*)dsm;
    float* Ws = sm;                       // [16][1024]
    float* xb = sm + QD_ * H_;            // [2][1024]
    __shared__ float zbuf[QD_];

    int tid = threadIdx.x, lane = tid & 31, w = tid >> 5;

    const float* WT = isq ? g_WqeT : g_WkeT;
    for (int idx = tid; idx < QD_ * H_; idx += 256)
        Ws[idx] = WT[idx];
    long long row0 = (long long)bid * ERB;

    float4 nxt = *(const float4*)&x[row0 * H_ + tid * 4];
    *(float4*)&xb[tid * 4] = nxt;
    if (isq) {
        half2* xp = (half2*)&g_xh[row0 * H_ + tid * 4];
        xp[0] = __floats2half2_rn(nxt.x, nxt.y);
        xp[1] = __floats2half2_rn(nxt.z, nxt.w);
    }
    __syncthreads();

    for (int r = 0; r < ERB; r++) {
        if (r + 1 < ERB) {
            nxt = *(const float4*)&x[(row0 + r + 1) * H_ + tid * 4];
            if (isq) {
                half2* xp = (half2*)&g_xh[(row0 + r + 1) * H_ + tid * 4];
                xp[0] = __floats2half2_rn(nxt.x, nxt.y);
                xp[1] = __floats2half2_rn(nxt.z, nxt.w);
            }
        }

        const float* xs = xb + (r & 1) * H_;
        float xr[32];
        #pragma unroll
        for (int i = 0; i < 8; i++)
            *(float4*)&xr[i * 4] = *(const float4*)&xs[i * 128 + lane * 4];

        #pragma unroll
        for (int oo = 0; oo < 2; oo++) {
            int o = w * 2 + oo;
            const float* wrow = Ws + o * H_;
            float s = 0.f;
            #pragma unroll
            for (int i = 0; i < 8; i++) {
                float4 wv = *(const float4*)&wrow[i * 128 + lane * 4];
                s += xr[i*4]*wv.x + xr[i*4+1]*wv.y + xr[i*4+2]*wv.z + xr[i*4+3]*wv.w;
            }
            #pragma unroll
            for (int off = 16; off; off >>= 1)
                s += __shfl_xor_sync(0xffffffffu, s, off);
            if (lane == 0) zbuf[o] = s;
        }
        __syncthreads();

        if (tid < 32) {
            int o = tid & 15;
            float z = zbuf[o] + (isq ? g_bqe[o] : g_bke[o]);
            float sq = z * z;
            #pragma unroll
            for (int off = 8; off; off >>= 1)
                sq += __shfl_xor_sync(0xffffffffu, sq, off);
            float val = z * rsqrtf(sq + 1e-8f);
            if (tid < QD_)
                (isq ? g_qq : g_kq)[(row0 + r) * QD_ + o] = val;
        }
        if (r + 1 < ERB)
            *(float4*)&xb[((r + 1) & 1) * H_ + tid * 4] = nxt;
        __syncthreads();
    }
}

__device__ __forceinline__ void attn_body(int bid)
{
    int b = bid >> 8;
    int q0 = (bid & 255) * 8;
    int tid = threadIdx.x;
    int lane = tid & 31, wid = tid >> 5;

    __shared__ float qs[8][QD_];
    __shared__ float red[8][9];

    if (tid < 128)
        ((float*)qs)[tid] = g_qq[((long long)b * S_ + q0) * QD_ + tid];
    __syncthreads();

    const float* kq = g_kq + (long long)b * S_ * QD_;
    float e[8][8];
    float sum[8] = {};

    #pragma unroll
    for (int j = 0; j < 8; j++) {
        int kk = tid + j * 256;
        const float4* kp = (const float4*)(kq + (long long)kk * QD_);
        float4 k0 = kp[0], k1 = kp[1], k2 = kp[2], k3 = kp[3];
        #pragma unroll
        for (int q = 0; q < 8; q++) {
            const float* qr = qs[q];
            float ov = qr[0]*k0.x + qr[1]*k0.y + qr[2]*k0.z + qr[3]*k0.w
                     + qr[4]*k1.x + qr[5]*k1.y + qr[6]*k1.z + qr[7]*k1.w
                     + qr[8]*k2.x + qr[9]*k2.y + qr[10]*k2.z + qr[11]*k2.w
                     + qr[12]*k3.x + qr[13]*k3.y + qr[14]*k3.z + qr[15]*k3.w;
            float ee = exp01(ov * ov);
            e[q][j] = ee;
            sum[q] += ee;
        }
    }

    #pragma unroll
    for (int q = 0; q < 8; q++) {
        float s = sum[q];
        #pragma unroll
        for (int off = 16; off; off >>= 1)
            s += __shfl_xor_sync(0xffffffffu, s, off);
        if (lane == 0) red[wid][q] = s;
    }
    __syncthreads();

    float inv[8];
    #pragma unroll
    for (int q = 0; q < 8; q++) {
        float t = 0.f;
        #pragma unroll
        for (int w = 0; w < 8; w++) t += red[w][q];
        inv[q] = 1.f / t;
    }

    #pragma unroll
    for (int q = 0; q < 8; q++) {
        long long rowo = ((long long)b * S_ + q0 + q) * S_;
        #pragma unroll
        for (int j = 0; j < 8; j++)
            g_attnh[rowo + tid + j * 256] = __float2half_rn(e[q][j] * inv[q]);
    }
}

// ---- split-fp16 GEMM body: CTA AMxBN, 8 warps (AM/2)x(BN/4), cp.async -----
#define APITCH 80

template<bool ASPLIT, bool BSPLIT, int AM, int BN>
__device__ __forceinline__ void load_stage(u32 sb,
    const half* __restrict__ Ah, const half* __restrict__ Al,
    const half* __restrict__ Bh, const half* __restrict__ Bl,
    int bm, int bn, int k0, int K, int N, int tid)
{
    constexpr int BPITCHc = BN * 2 + 16;
    constexpr int BTILEc  = 32 * BPITCHc;
    constexpr int ATILEc  = AM * APITCH;
    constexpr int BOFF    = ATILEc * (ASPLIT ? 2 : 1);
    #pragma unroll
    for (int i = 0; i < AM / 64; i++) {
        int u = tid + i * 256;
        int r = u >> 2, c = u & 3;
        long long g = (long long)(bm + r) * K + k0 + c * 8;
        cpa16(sb + r * APITCH + c * 16, Ah + g);
        if (ASPLIT) cpa16(sb + ATILEc + r * APITCH + c * 16, Al + g);
    }
    #pragma unroll
    for (int i = 0; i < BN / 64; i++) {
        int u = tid + i * 256;
        int r = u / (BN / 8), c = u % (BN / 8);
        long long g = (long long)(k0 + r) * N + bn + c * 8;
        cpa16(sb + BOFF + r * BPITCHc + c * 16, Bh + g);
        if (BSPLIT) cpa16(sb + BOFF + BTILEc + r * BPITCHc + c * 16, Bl + g);
    }
}

template<bool ASPLIT, bool BSPLIT, int OMODE, int STAGES, int AM, int BN>
__device__ __forceinline__ void gemm_body(
    const half* __restrict__ Ah, const half* __restrict__ Al,
    const half* __restrict__ Bh, const half* __restrict__ Bl,
    const float* __restrict__ bias,
    float* __restrict__ Cf, half* __restrict__ Ch,
    int bm, int bn, int N, int K)
{
    constexpr int BPITCHc = BN * 2 + 16;
    constexpr int BTILEc  = 32 * BPITCHc;
    constexpr int ATILEc  = AM * APITCH;
    constexpr int BOFF    = ATILEc * (ASPLIT ? 2 : 1);
    constexpr int STG     = BOFF + BTILEc * (BSPLIT ? 2 : 1);
    constexpr int MT      = AM / 32;        // 16-row m-tiles per warp
    constexpr int WN      = BN / 4;         // per-warp n width
    constexpr int NT      = WN / 16;        // ldsm4t tiles per warp
    constexpr int JN      = WN / 8;         // 8-col mma tiles per warp

    extern __shared__ char dsm[];
    u32 sbase = smem_u32(dsm);

    const int tid = threadIdx.x;
    const int wid = tid >> 5, lane = tid & 31;
    const int wm = (wid >> 2) * (AM / 2);
    const int wn = (wid & 3) * WN;

    float acc[MT][JN][4] = {};

    const int NC = K >> 5;
    #pragma unroll
    for (int s = 0; s < STAGES - 1; s++) {
        load_stage<ASPLIT, BSPLIT, AM, BN>(sbase + s * STG, Ah, Al, Bh, Bl,
                                           bm, bn, s << 5, K, N, tid);
        CP_COMMIT();
    }

    const int arow = lane & 15;
    const int ak8  = ((lane >> 4) & 1) * 8;
    const int bk   = lane & 15;
    const int bn8  = ((lane >> 4) & 1) * 8;

    int ld = STAGES - 1;
    for (int c = 0; c < NC; c++) {
        CP_WAIT(STAGES - 2);
        __syncthreads();

        if (ld < NC) {
            load_stage<ASPLIT, BSPLIT, AM, BN>(sbase + (ld % STAGES) * STG,
                Ah, Al, Bh, Bl, bm, bn, ld << 5, K, N, tid);
            ld++;
        }
        // ALWAYS commit (possibly-empty group): keeps the group ledger deep
        // enough that the tail CP_WAIT(STAGES-2) actually drains the final
        // stage's loads. (Fixes latent race present since R6.)
        CP_COMMIT();

        u32 st = sbase + (c % STAGES) * STG;
        u32 As = st, Als = st + ATILEc;
        u32 Bs = st + BOFF, Bls = Bs + BTILEc;

        #pragma unroll
        for (int ks = 0; ks < 32; ks += 16) {
            u32 bh[NT][4], bl[NT][4];
            #pragma unroll
            for (int n2 = 0; n2 < NT; n2++) {
                u32 boff = (ks + bk) * BPITCHc + (wn + 16 * n2 + bn8) * 2;
                ldsm4t(bh[n2], Bs + boff);
                if (BSPLIT) ldsm4t(bl[n2], Bls + boff);
            }
            #pragma unroll
            for (int m = 0; m < MT; m++) {
                u32 ah[4], al[4];
                u32 aoff = (wm + 16 * m + arow) * APITCH + (ks + ak8) * 2;
                ldsm4(ah, As + aoff);
                if (ASPLIT) ldsm4(al, Als + aoff);
                #pragma unroll
                for (int j = 0; j < JN; j++) {
                    const u32* bhp = &bh[j >> 1][(j & 1) * 2];
                    mma16816(acc[m][j], ah, bhp);
                    if (ASPLIT) mma16816(acc[m][j], al, bhp);
                    if (BSPLIT) {
                        const u32* blp = &bl[j >> 1][(j & 1) * 2];
                        mma16816(acc[m][j], ah, blp);
                    }
                }
            }
        }
    }

    const int trow = lane >> 2;
    const int tcol = (lane & 3) * 2;

    #pragma unroll
    for (int m = 0; m < MT; m++) {
        #pragma unroll
        for (int j = 0; j < JN; j++) {
            int col = bn + wn + 8 * j + tcol;
            float b0 = bias ? bias[col] : 0.f;
            float b1 = bias ? bias[col + 1] : 0.f;
            #pragma unroll
            for (int h = 0; h < 2; h++) {
                long long row = bm + wm + 16 * m + trow + h * 8;
                float v0 = acc[m][j][2 * h + 0] + b0;
                float v1 = acc[m][j][2 * h + 1] + b1;
                long long idx = row * N + col;
                if (OMODE == 0)
                    *(float2*)(Cf + idx) = make_float2(v0, v1);
                else
                    *(half2*)(Ch + idx) = __floats2half2_rn(v0, v1);
            }
        }
    }
}

// ------------------------------ fat kernels --------------------------------

// L1: precompute(257) || b2(32) || weight hi+lo splits(2048)
__global__ __launch_bounds__(256)
void prep_kernel(const float* __restrict__ Wq, const float* __restrict__ Wk,
                 const float* __restrict__ We, const float* __restrict__ bq,
                 const float* __restrict__ bk, const float* __restrict__ be,
                 const float* __restrict__ bv, const float* __restrict__ Wv,
                 const float* __restrict__ Wo)
{
    int bid = blockIdx.x;
    if (bid < 257)       precompute_body(bid, Wq, Wk, We, bq, bk, be);
    else if (bid < 289)  b2_body(bid - 257, bv, Wo);
    else                 split_body(bid - 289, Wv, Wo);
}

// L2: W2 = Wv@Wo 3-term (128 CTAs of 64x128) || embed-q(128) || embed-k(128)
__global__ __launch_bounds__(256, 2)
void embed_w2_kernel(const float* __restrict__ x)
{
    int bid = blockIdx.x;
    if (bid < 128) {
        gemm_body<true, true, 2, 2, 64, 128>(g_Wvh, g_Wvl, g_Woh, g_Wol,
                                             nullptr, nullptr, g_W2h,
                                             (bid >> 3) * 64, (bid & 7) * 128, H_, H_);
    } else if (bid < 256) {
        embed_body16(bid - 128, x, true);
    } else {
        embed_body16(bid - 256, x, false);
    }
}

// L3: v2 = xh@W2h + b2 (1024 CTAs of 64x128, 3 CTAs/SM) || attn(1024)
__global__ __launch_bounds__(256, 3)
void attn_v2_kernel()
{
    int bid = blockIdx.x;
    if (bid < 1024) {
        gemm_body<false, false, 2, 3, 64, 128>(g_xh, nullptr, g_W2h, nullptr,
                                               g_b2, nullptr, g_v2h,
                                               (bid >> 3) * 64, (bid & 7) * 128, H_, H_);
    } else {
        attn_body(bid - 1024);
    }
}

// L4: out = attn @ v2 + bo (1024 CTAs of 64x128: 32 bm x 8 bn x 4 z)
__global__ __launch_bounds__(256, 3)
void out_kernel(const float* __restrict__ bo, float* __restrict__ out)
{
    int t = blockIdx.x;
    int z = t >> 8;
    int r = t & 255;
    gemm_body<false, false, 0, 3, 64, 128>(
        g_attnh + (long long)z * S_ * S_, nullptr,
        g_v2h + (long long)z * S_ * H_, nullptr,
        bo, out + (long long)z * S_ * H_, nullptr,
        (r >> 3) * 64, (r & 7) * 128, H_, S_);
}

// ---------------------------------------------------------------------------
extern "C" void kernel_launch(void* const* d_in, const int* in_sizes, int n_in,
                              void* d_out, int out_size)
{
    const float* x  = (const float*)d_in[0];
    const float* Wq = (const float*)d_in[1];
    const float* bq = (const float*)d_in[2];
    const float* Wk = (const float*)d_in[3];
    const float* bk = (const float*)d_in[4];
    const float* Wv = (const float*)d_in[5];
    const float* bv = (const float*)d_in[6];
    const float* We = (const float*)d_in[7];
    const float* be = (const float*)d_in[8];
    const float* Wo = (const float*)d_in[9];
    const float* bo = (const float*)d_in[10];
    float* out = (float*)d_out;

    const int SM_L1 = H_ * 17 * 4;                       // 69632 (precompute)
    const int SM_L2 = (QD_ * H_ + 2 * H_) * 4;           // 73728 (embed16; W2 needs 55296)
    const int SM_L3 = 3 * (64 * APITCH + 32 * (128 * 2 + 16));  // 41472
    const int SM_L4 = SM_L3;

    cudaFuncSetAttribute(prep_kernel,     cudaFuncAttributeMaxDynamicSharedMemorySize, SM_L1);
    cudaFuncSetAttribute(embed_w2_kernel, cudaFuncAttributeMaxDynamicSharedMemorySize, SM_L2);
    cudaFuncSetAttribute(attn_v2_kernel,  cudaFuncAttributeMaxDynamicSharedMemorySize, SM_L3);
    cudaFuncSetAttribute(out_kernel,      cudaFuncAttributeMaxDynamicSharedMemorySize, SM_L4);

    prep_kernel<<<257 + 32 + 2048, 256, SM_L1>>>(Wq, Wk, We, bq, bk, be, bv, Wv, Wo);
    embed_w2_kernel<<<128 + 128 + 128, 256, SM_L2>>>(x);
    attn_v2_kernel<<<1024 + 1024, 256, SM_L3>>>();
    out_kernel<<<1024, 256, SM_L4>>>(bo, out);
}